// round 1
// baseline (speedup 1.0000x reference)
#include <cuda_runtime.h>
#include <cstddef>

#define NN 100000
#define EE 1600000
#define C  128

// ---- scratch (device globals: allocation-free) ----
__device__ float g_agg[(size_t)NN * C];   // 51.2 MB
__device__ float g_h1 [(size_t)NN * C];   // 51.2 MB
__device__ float g_h2 [(size_t)NN * C];   // 51.2 MB
__device__ int   g_cnt[NN];

// ---------------------------------------------------------------------------
// zero fill (float4)
// ---------------------------------------------------------------------------
__global__ void zero_f4(float4* __restrict__ p, int n4) {
    int i = blockIdx.x * blockDim.x + threadIdx.x;
    if (i < n4) p[i] = make_float4(0.f, 0.f, 0.f, 0.f);
}

// ---------------------------------------------------------------------------
// edge scatter: one warp per edge. Gather feat[src] row (128 f32 = 32 lanes x
// float4), vector-reduce into agg[dst]. Optionally count in-degree (lane 0).
// ---------------------------------------------------------------------------
__global__ __launch_bounds__(256) void scatter_edges(
    const float* __restrict__ feat,
    const int*   __restrict__ src,
    const int*   __restrict__ dst,
    float*       __restrict__ agg,
    int*         __restrict__ cnt)
{
    int gw   = (blockIdx.x * blockDim.x + threadIdx.x) >> 5;
    int lane = threadIdx.x & 31;
    if (gw >= EE) return;

    int s = __ldg(src + gw);
    int d = __ldg(dst + gw);

    float4 v = __ldg((const float4*)(feat + (size_t)s * C) + lane);
    float* p = agg + (size_t)d * C + lane * 4;
#if __CUDA_ARCH__ >= 900
    asm volatile("red.global.add.v4.f32 [%0], {%1, %2, %3, %4};"
                 :: "l"(p), "f"(v.x), "f"(v.y), "f"(v.z), "f"(v.w) : "memory");
#else
    atomicAdd(p + 0, v.x); atomicAdd(p + 1, v.y);
    atomicAdd(p + 2, v.z); atomicAdd(p + 3, v.w);
#endif
    if (cnt != nullptr && lane == 0) atomicAdd(cnt + d, 1);
}

// ---------------------------------------------------------------------------
// fused dual-matmul layer:
//   out[n][o] = relu( sum_k A'[n][k]*Wa[o][k] + B[n][k]*Wb[o][k] + bias[o] )
// where A' = A * (1/max(cnt,1)) when SCALE_A (mean aggregation).
//
// Tile: 64 nodes x 128 outputs per 256-thread block.
// SMEM: Wa,Wb transposed to [k][o] (pitch 132 -> float4-aligned rows),
//       A,B node tiles [64][128]. Total 196 KB dynamic smem.
// Microtile: 8 nodes x 4 outputs per thread (32 fp32 accumulators).
// ---------------------------------------------------------------------------
#define WPITCH 132
#define TN 64

template <bool SCALE_A>
__global__ __launch_bounds__(256, 1) void fused_layer(
    const float* __restrict__ A,
    const float* __restrict__ B,
    const float* __restrict__ Wa, int lda,
    const float* __restrict__ Wb, int ldb,
    const float* __restrict__ bias,
    const int*   __restrict__ cnt,
    float*       __restrict__ out,
    int nrows)
{
    extern __shared__ float sm[];
    float* Wsa = sm;                       // [128][WPITCH]
    float* Wsb = sm + C * WPITCH;          // [128][WPITCH]
    float* As  = sm + 2 * C * WPITCH;      // [64][128]
    float* Bs  = As + TN * C;              // [64][128]

    const int t = threadIdx.x;

    // stage weights transposed: Ws[k][o] = W[o][k]
    for (int i = t; i < C * C; i += 256) {
        int o = i >> 7, k = i & (C - 1);
        Wsa[k * WPITCH + o] = __ldg(Wa + (size_t)o * lda + k);
        Wsb[k * WPITCH + o] = __ldg(Wb + (size_t)o * ldb + k);
    }

    const int nb = blockIdx.x * TN;

    // stage A/B node tiles (float4), fusing 1/deg scaling into A
    for (int i = t; i < TN * (C / 4); i += 256) {  // 2048 float4
        int n  = i >> 5;        // 32 float4 per row
        int c4 = i & 31;
        int gn = nb + n;
        float4 va = make_float4(0.f, 0.f, 0.f, 0.f);
        float4 vb = va;
        if (gn < nrows) {
            va = __ldg((const float4*)(A + (size_t)gn * C) + c4);
            vb = __ldg((const float4*)(B + (size_t)gn * C) + c4);
            if (SCALE_A) {
                int cc = __ldg(cnt + gn);
                float s = 1.f / (float)(cc > 1 ? cc : 1);
                va.x *= s; va.y *= s; va.z *= s; va.w *= s;
            }
        }
        *((float4*)(As + n * C) + c4) = va;
        *((float4*)(Bs + n * C) + c4) = vb;
    }
    __syncthreads();

    const int lane = t & 31;
    const int warp = t >> 5;

    float acc[8][4];
#pragma unroll
    for (int r = 0; r < 8; r++) {
        acc[r][0] = 0.f; acc[r][1] = 0.f; acc[r][2] = 0.f; acc[r][3] = 0.f;
    }

    const float* arow = As + (warp * 8) * C;
    const float* brow = Bs + (warp * 8) * C;

#pragma unroll 4
    for (int k = 0; k < C; k++) {
        float4 wa = *(const float4*)(Wsa + k * WPITCH + lane * 4);
        float4 wb = *(const float4*)(Wsb + k * WPITCH + lane * 4);
#pragma unroll
        for (int r = 0; r < 8; r++) {
            float a = arow[r * C + k];
            float b = brow[r * C + k];
            acc[r][0] = fmaf(a, wa.x, acc[r][0]);
            acc[r][1] = fmaf(a, wa.y, acc[r][1]);
            acc[r][2] = fmaf(a, wa.z, acc[r][2]);
            acc[r][3] = fmaf(a, wa.w, acc[r][3]);
            acc[r][0] = fmaf(b, wb.x, acc[r][0]);
            acc[r][1] = fmaf(b, wb.y, acc[r][1]);
            acc[r][2] = fmaf(b, wb.z, acc[r][2]);
            acc[r][3] = fmaf(b, wb.w, acc[r][3]);
        }
    }

    float4 bi = __ldg((const float4*)bias + lane);
#pragma unroll
    for (int r = 0; r < 8; r++) {
        int gn = nb + warp * 8 + r;
        if (gn < nrows) {
            float4 o;
            o.x = fmaxf(acc[r][0] + bi.x, 0.f);
            o.y = fmaxf(acc[r][1] + bi.y, 0.f);
            o.z = fmaxf(acc[r][2] + bi.z, 0.f);
            o.w = fmaxf(acc[r][3] + bi.w, 0.f);
            *((float4*)(out + (size_t)gn * C) + lane) = o;
        }
    }
}

// ---------------------------------------------------------------------------
// launch
// ---------------------------------------------------------------------------
extern "C" void kernel_launch(void* const* d_in, const int* in_sizes, int n_in,
                              void* d_out, int out_size)
{
    const float* x    = (const float*)d_in[0];
    const int*   ei   = (const int*)  d_in[1];
    const float* Wl1  = (const float*)d_in[2];
    const float* Wr1  = (const float*)d_in[3];
    const float* b1   = (const float*)d_in[4];
    const float* Wl2  = (const float*)d_in[5];
    const float* Wr2  = (const float*)d_in[6];
    const float* b2   = (const float*)d_in[7];
    const float* Wlin = (const float*)d_in[8];
    const float* blin = (const float*)d_in[9];
    float*       out  = (float*)d_out;

    const int* src = ei;
    const int* dst = ei + EE;

    void *agg_v, *h1_v, *h2_v, *cnt_v;
    cudaGetSymbolAddress(&agg_v, g_agg);
    cudaGetSymbolAddress(&h1_v,  g_h1);
    cudaGetSymbolAddress(&h2_v,  g_h2);
    cudaGetSymbolAddress(&cnt_v, g_cnt);
    float* agg = (float*)agg_v;
    float* h1  = (float*)h1_v;
    float* h2  = (float*)h2_v;
    int*   cnt = (int*)cnt_v;

    const int SMEM = (2 * C * WPITCH + 2 * TN * C) * (int)sizeof(float); // 200704 B
    cudaFuncSetAttribute(fused_layer<true>,
                         cudaFuncAttributeMaxDynamicSharedMemorySize, SMEM);
    cudaFuncSetAttribute(fused_layer<false>,
                         cudaFuncAttributeMaxDynamicSharedMemorySize, SMEM);

    const int featN4 = NN * C / 4;                 // 3,200,000
    const int zb     = (featN4 + 255) / 256;
    const int cntN4  = NN / 4;                     // 25,000
    const int zcb    = (cntN4 + 255) / 256;
    const int sblk   = EE / 8;                     // 200,000 (8 warps/block)
    const int gblk   = (NN + TN - 1) / TN;         // 1563

    // ---- conv1 ----
    zero_f4<<<zb, 256>>>((float4*)agg, featN4);
    zero_f4<<<zcb, 256>>>((float4*)cnt, cntN4);
    scatter_edges<<<sblk, 256>>>(x, src, dst, agg, cnt);
    fused_layer<true><<<gblk, 256, SMEM>>>(agg, x, Wl1, C, Wr1, C, b1, cnt, h1, NN);

    // ---- conv2 ----
    zero_f4<<<zb, 256>>>((float4*)agg, featN4);
    scatter_edges<<<sblk, 256>>>(h1, src, dst, agg, nullptr);
    fused_layer<true><<<gblk, 256, SMEM>>>(agg, h1, Wl2, C, Wr2, C, b2, cnt, h2, NN);

    // ---- JK-cat + linear head: Wa = Wlin[:, :128], Wb = Wlin[:, 128:] ----
    fused_layer<false><<<gblk, 256, SMEM>>>(h1, h2, Wlin, 2 * C, Wlin + C, 2 * C,
                                            blin, nullptr, out, NN);
}

// round 3
// speedup vs baseline: 1.0857x; 1.0857x over previous
#include <cuda_runtime.h>
#include <cuda_bf16.h>
#include <cstdint>
#include <cstddef>

#define NN 100000
#define EE 1600000
#define C  128

// ---- scratch (device globals: allocation-free) ----
__device__ float g_agg[(size_t)NN * C];
__device__ float g_h1 [(size_t)NN * C];
__device__ float g_h2 [(size_t)NN * C];
__device__ int   g_cnt[NN];

// ---------------------------------------------------------------------------
// zero fill
// ---------------------------------------------------------------------------
__global__ void zero_f4(float4* __restrict__ p, int n4) {
    int i = blockIdx.x * blockDim.x + threadIdx.x;
    if (i < n4) p[i] = make_float4(0.f, 0.f, 0.f, 0.f);
}

// ---------------------------------------------------------------------------
// edge scatter: one warp per edge, red.global.add.v4.f32
// ---------------------------------------------------------------------------
__global__ __launch_bounds__(256) void scatter_edges(
    const float* __restrict__ feat,
    const int*   __restrict__ src,
    const int*   __restrict__ dst,
    float*       __restrict__ agg,
    int*         __restrict__ cnt)
{
    int gw   = (blockIdx.x * blockDim.x + threadIdx.x) >> 5;
    int lane = threadIdx.x & 31;
    if (gw >= EE) return;

    int s = __ldg(src + gw);
    int d = __ldg(dst + gw);

    float4 v = __ldg((const float4*)(feat + (size_t)s * C) + lane);
    float* p = agg + (size_t)d * C + lane * 4;
    asm volatile("red.global.add.v4.f32 [%0], {%1, %2, %3, %4};"
                 :: "l"(p), "f"(v.x), "f"(v.y), "f"(v.z), "f"(v.w) : "memory");
    if (cnt != nullptr && lane == 0) atomicAdd(cnt + d, 1);
}

// ---------------------------------------------------------------------------
// HMMA fused dual-matmul layer (split-bf16 emulated fp32):
//   out[n][o] = relu( A1'[n][:]·W1[o][:] + A2[n][:]·W2[o][:] + bias[o] )
// A1' = A1/max(cnt,1) when cnt != nullptr.
//
// Block: 256 thr (8 warps), tile 128 nodes x 128 outs, K in 2 passes of 128.
// Warp tile 32x64: 2 m-tiles x 8 n-tiles of m16n8k16 mma.sync bf16.
// Split-bf16: acc += Ah*Wh + Al*Wh + Ah*Wl  (3 MMAs per tile per k-step).
//
// SMEM: 4 slabs [128 rows][APITCH=136 bf16] (hi/lo for A and W), 136 KB.
// Pitch 136 => row bank-stride 4 => conflict-free fragment loads.
// ---------------------------------------------------------------------------
#define APITCH 136
#define SLAB_B (128 * APITCH * 2)            // 34816 bytes
#define AH_OFF 0
#define AL_OFF SLAB_B
#define BH_OFF (2 * SLAB_B)
#define BL_OFF (3 * SLAB_B)
#define SMEM_BYTES (4 * SLAB_B)              // 139264

__device__ __forceinline__ void mma16816(float* c, const uint32_t* a, const uint32_t* b) {
    asm volatile(
        "mma.sync.aligned.m16n8k16.row.col.f32.bf16.bf16.f32 "
        "{%0,%1,%2,%3}, {%4,%5,%6,%7}, {%8,%9}, {%0,%1,%2,%3};"
        : "+f"(c[0]), "+f"(c[1]), "+f"(c[2]), "+f"(c[3])
        : "r"(a[0]), "r"(a[1]), "r"(a[2]), "r"(a[3]), "r"(b[0]), "r"(b[1]));
}

__global__ __launch_bounds__(256, 1) void hmma_layer(
    const float* __restrict__ A1, const float* __restrict__ W1, int ld1,
    const float* __restrict__ A2, const float* __restrict__ W2, int ld2,
    const float* __restrict__ bias, const int* __restrict__ cnt,
    float* __restrict__ out, int nrows)
{
    extern __shared__ char sm[];
    const int t    = threadIdx.x;
    const int wid  = t >> 5;
    const int lane = t & 31;
    const int nb   = blockIdx.x * 128;

    const int mBase = (wid & 3) * 32;   // 4 M-warps
    const int nBase = (wid >> 2) * 64;  // 2 N-warps
    const int qrow  = lane >> 2;        // 0..7
    const int qk    = (lane & 3) * 2;   // 0,2,4,6

    float acc[2][8][4];
#pragma unroll
    for (int mt = 0; mt < 2; mt++)
#pragma unroll
        for (int nt = 0; nt < 8; nt++)
#pragma unroll
            for (int j = 0; j < 4; j++) acc[mt][nt][j] = 0.f;

#pragma unroll 1
    for (int pass = 0; pass < 2; pass++) {
        const float* A  = pass ? A2 : A1;
        const float* W  = pass ? W2 : W1;
        const int    ld = pass ? ld2 : ld1;
        const bool   scale = (pass == 0) && (cnt != nullptr);

        // ---- stage: fp32 -> (hi, lo) bf16 slabs ----
        for (int i = t; i < 8192; i += 256) {
            const int isW = (i >= 4096);
            const int g   = i & 4095;
            const int row = g >> 5;        // 0..127
            const int f4  = g & 31;
            const int k0  = f4 * 4;

            float4 v;
            if (!isW) {
                const int gn = nb + row;
                if (gn < nrows) {
                    v = __ldg((const float4*)(A + (size_t)gn * C + k0));
                    if (scale) {
                        int cc = __ldg(cnt + gn);
                        float s = 1.f / (float)(cc > 1 ? cc : 1);
                        v.x *= s; v.y *= s; v.z *= s; v.w *= s;
                    }
                } else {
                    v = make_float4(0.f, 0.f, 0.f, 0.f);
                }
            } else {
                v = __ldg((const float4*)(W + (size_t)row * ld + k0));
            }

            float f[4] = {v.x, v.y, v.z, v.w};
            uint32_t hi[2], lo[2];
#pragma unroll
            for (int j = 0; j < 2; j++) {
                __nv_bfloat16 h0 = __float2bfloat16(f[2 * j]);
                __nv_bfloat16 h1 = __float2bfloat16(f[2 * j + 1]);
                float r0 = f[2 * j]     - __bfloat162float(h0);
                float r1 = f[2 * j + 1] - __bfloat162float(h1);
                __nv_bfloat16 l0 = __float2bfloat16(r0);
                __nv_bfloat16 l1 = __float2bfloat16(r1);
                hi[j] = (uint32_t)__bfloat16_as_ushort(h0) |
                        ((uint32_t)__bfloat16_as_ushort(h1) << 16);
                lo[j] = (uint32_t)__bfloat16_as_ushort(l0) |
                        ((uint32_t)__bfloat16_as_ushort(l1) << 16);
            }

            const size_t eoff = ((size_t)row * APITCH + k0) * 2;
            const size_t hbase = isW ? BH_OFF : AH_OFF;
            const size_t lbase = isW ? BL_OFF : AL_OFF;
            *(uint2*)(sm + hbase + eoff) = make_uint2(hi[0], hi[1]);
            *(uint2*)(sm + lbase + eoff) = make_uint2(lo[0], lo[1]);
        }
        __syncthreads();

        // ---- MMA: 8 k16 steps over this 128-wide K chunk ----
#define LD32(base, row, k) \
    (*(const uint32_t*)(sm + (base) + ((size_t)(row) * APITCH + (k)) * 2))

#pragma unroll
        for (int ks = 0; ks < 8; ks++) {
            const int k = ks * 16 + qk;

            uint32_t ah[2][4], al[2][4];
#pragma unroll
            for (int mt = 0; mt < 2; mt++) {
                const int r = mBase + mt * 16 + qrow;
                ah[mt][0] = LD32(AH_OFF, r,     k);
                ah[mt][1] = LD32(AH_OFF, r + 8, k);
                ah[mt][2] = LD32(AH_OFF, r,     k + 8);
                ah[mt][3] = LD32(AH_OFF, r + 8, k + 8);
                al[mt][0] = LD32(AL_OFF, r,     k);
                al[mt][1] = LD32(AL_OFF, r + 8, k);
                al[mt][2] = LD32(AL_OFF, r,     k + 8);
                al[mt][3] = LD32(AL_OFF, r + 8, k + 8);
            }

#pragma unroll
            for (int nt = 0; nt < 8; nt++) {
                const int cl = nBase + nt * 8 + qrow;
                uint32_t bh[2], bl[2];
                bh[0] = LD32(BH_OFF, cl, k);
                bh[1] = LD32(BH_OFF, cl, k + 8);
                bl[0] = LD32(BL_OFF, cl, k);
                bl[1] = LD32(BL_OFF, cl, k + 8);
#pragma unroll
                for (int mt = 0; mt < 2; mt++) {
                    mma16816(acc[mt][nt], ah[mt], bh);
                    mma16816(acc[mt][nt], al[mt], bh);
                    mma16816(acc[mt][nt], ah[mt], bl);
                }
            }
        }
#undef LD32
        __syncthreads();
    }

    // ---- epilogue: bias + relu, direct register -> gmem (float2 stores) ----
#pragma unroll
    for (int nt = 0; nt < 8; nt++) {
        const int cl = nBase + nt * 8 + qk;
        const float2 b = __ldg((const float2*)(bias + cl));
#pragma unroll
        for (int mt = 0; mt < 2; mt++) {
            const int r0 = nb + mBase + mt * 16 + qrow;
            if (r0 < nrows) {
                float2 o;
                o.x = fmaxf(acc[mt][nt][0] + b.x, 0.f);
                o.y = fmaxf(acc[mt][nt][1] + b.y, 0.f);
                *(float2*)(out + (size_t)r0 * C + cl) = o;
            }
            const int r1 = r0 + 8;
            if (r1 < nrows) {
                float2 o;
                o.x = fmaxf(acc[mt][nt][2] + b.x, 0.f);
                o.y = fmaxf(acc[mt][nt][3] + b.y, 0.f);
                *(float2*)(out + (size_t)r1 * C + cl) = o;
            }
        }
    }
}

// ---------------------------------------------------------------------------
// launch
// ---------------------------------------------------------------------------
extern "C" void kernel_launch(void* const* d_in, const int* in_sizes, int n_in,
                              void* d_out, int out_size)
{
    const float* x    = (const float*)d_in[0];
    const int*   ei   = (const int*)  d_in[1];
    const float* Wl1  = (const float*)d_in[2];
    const float* Wr1  = (const float*)d_in[3];
    const float* b1   = (const float*)d_in[4];
    const float* Wl2  = (const float*)d_in[5];
    const float* Wr2  = (const float*)d_in[6];
    const float* b2   = (const float*)d_in[7];
    const float* Wlin = (const float*)d_in[8];
    const float* blin = (const float*)d_in[9];
    float*       out  = (float*)d_out;

    const int* src = ei;
    const int* dst = ei + EE;

    void *agg_v, *h1_v, *h2_v, *cnt_v;
    cudaGetSymbolAddress(&agg_v, g_agg);
    cudaGetSymbolAddress(&h1_v,  g_h1);
    cudaGetSymbolAddress(&h2_v,  g_h2);
    cudaGetSymbolAddress(&cnt_v, g_cnt);
    float* agg = (float*)agg_v;
    float* h1  = (float*)h1_v;
    float* h2  = (float*)h2_v;
    int*   cnt = (int*)cnt_v;

    cudaFuncSetAttribute(hmma_layer,
                         cudaFuncAttributeMaxDynamicSharedMemorySize, SMEM_BYTES);

    const int featN4 = NN * C / 4;
    const int zb     = (featN4 + 255) / 256;
    const int cntN4  = NN / 4;
    const int zcb    = (cntN4 + 255) / 256;
    const int sblk   = EE / 8;
    const int gblk   = (NN + 127) / 128;   // 782

    // ---- conv1 ----
    zero_f4<<<zb, 256>>>((float4*)agg, featN4);
    zero_f4<<<zcb, 256>>>((float4*)cnt, cntN4);
    scatter_edges<<<sblk, 256>>>(x, src, dst, agg, cnt);
    hmma_layer<<<gblk, 256, SMEM_BYTES>>>(agg, Wl1, C, x, Wr1, C, b1, cnt, h1, NN);

    // ---- conv2 ----
    zero_f4<<<zb, 256>>>((float4*)agg, featN4);
    scatter_edges<<<sblk, 256>>>(h1, src, dst, agg, nullptr);
    hmma_layer<<<gblk, 256, SMEM_BYTES>>>(agg, Wl2, C, h1, Wr2, C, b2, cnt, h2, NN);

    // ---- JK-cat + linear head ----
    hmma_layer<<<gblk, 256, SMEM_BYTES>>>(h1, Wlin, 2 * C, h2, Wlin + C, 2 * C,
                                          blin, nullptr, out, NN);
}

// round 4
// speedup vs baseline: 1.5730x; 1.4489x over previous
#include <cuda_runtime.h>
#include <cuda_bf16.h>
#include <cstdint>
#include <cstddef>

#define NN 100000
#define EE 1600000
#define C  128

// ---- scratch (device globals: allocation-free) ----
__device__ float g_agg[(size_t)NN * C];
__device__ float g_h1 [(size_t)NN * C];
__device__ float g_h2 [(size_t)NN * C];
__device__ int   g_cnt[NN];
__device__ __nv_bfloat16 g_whi[6 * 16384];   // pre-split weights (hi)
__device__ __nv_bfloat16 g_wlo[6 * 16384];   // pre-split weights (lo)

// ---------------------------------------------------------------------------
// helpers
// ---------------------------------------------------------------------------
__device__ __forceinline__ uint32_t smem_u32(const void* p) {
    uint32_t a;
    asm("{ .reg .u64 t; cvta.to.shared.u64 t, %1; cvt.u32.u64 %0, t; }"
        : "=r"(a) : "l"(p));
    return a;
}
__device__ __forceinline__ void cp16(uint32_t saddr, const void* g) {
    asm volatile("cp.async.cg.shared.global [%0], [%1], 16;"
                 :: "r"(saddr), "l"(g) : "memory");
}
__device__ __forceinline__ void ldsm4(uint32_t addr, uint32_t* r) {
    asm volatile("ldmatrix.sync.aligned.m8n8.x4.shared.b16 {%0,%1,%2,%3}, [%4];"
                 : "=r"(r[0]), "=r"(r[1]), "=r"(r[2]), "=r"(r[3]) : "r"(addr));
}
__device__ __forceinline__ void mma16816(float* c, const uint32_t* a, const uint32_t* b) {
    asm volatile(
        "mma.sync.aligned.m16n8k16.row.col.f32.bf16.bf16.f32 "
        "{%0,%1,%2,%3}, {%4,%5,%6,%7}, {%8,%9}, {%0,%1,%2,%3};"
        : "+f"(c[0]), "+f"(c[1]), "+f"(c[2]), "+f"(c[3])
        : "r"(a[0]), "r"(a[1]), "r"(a[2]), "r"(a[3]), "r"(b[0]), "r"(b[1]));
}
// pack two floats to bf16x2 (elem0 -> low half)
__device__ __forceinline__ uint32_t packbf2(float f0, float f1) {
    uint32_t r;
    asm("cvt.rn.bf16x2.f32 %0, %1, %2;" : "=r"(r) : "f"(f1), "f"(f0));
    return r;
}

// ---------------------------------------------------------------------------
// zero fill
// ---------------------------------------------------------------------------
__global__ void zero_f4(float4* __restrict__ p, int n4) {
    int i = blockIdx.x * blockDim.x + threadIdx.x;
    if (i < n4) p[i] = make_float4(0.f, 0.f, 0.f, 0.f);
}

// ---------------------------------------------------------------------------
// one-shot weight split: 6 slabs of [128][128] fp32 -> hi/lo bf16
// slabs: 0=Wl1 1=Wr1 2=Wl2 3=Wr2 4=Wlin[:, :128] 5=Wlin[:, 128:]
// ---------------------------------------------------------------------------
__global__ void split_weights(const float* __restrict__ Wl1, const float* __restrict__ Wr1,
                              const float* __restrict__ Wl2, const float* __restrict__ Wr2,
                              const float* __restrict__ Wlin,
                              __nv_bfloat16* __restrict__ whi,
                              __nv_bfloat16* __restrict__ wlo)
{
    int i = blockIdx.x * blockDim.x + threadIdx.x;
    if (i >= 6 * 16384) return;
    int s = i >> 14, r = (i >> 7) & 127, k = i & 127;
    float v;
    switch (s) {
        case 0:  v = __ldg(Wl1 + r * 128 + k); break;
        case 1:  v = __ldg(Wr1 + r * 128 + k); break;
        case 2:  v = __ldg(Wl2 + r * 128 + k); break;
        case 3:  v = __ldg(Wr2 + r * 128 + k); break;
        case 4:  v = __ldg(Wlin + r * 256 + k); break;
        default: v = __ldg(Wlin + r * 256 + 128 + k); break;
    }
    __nv_bfloat16 h = __float2bfloat16(v);
    whi[i] = h;
    wlo[i] = __float2bfloat16(v - __bfloat162float(h));
}

// ---------------------------------------------------------------------------
// edge scatter: one warp per edge, red.global.add.v4.f32
// ---------------------------------------------------------------------------
__global__ __launch_bounds__(256) void scatter_edges(
    const float* __restrict__ feat,
    const int*   __restrict__ src,
    const int*   __restrict__ dst,
    float*       __restrict__ agg,
    int*         __restrict__ cnt)
{
    int gw   = (blockIdx.x * blockDim.x + threadIdx.x) >> 5;
    int lane = threadIdx.x & 31;
    if (gw >= EE) return;

    int s = __ldg(src + gw);
    int d = __ldg(dst + gw);

    float4 v = __ldg((const float4*)(feat + (size_t)s * C) + lane);
    float* p = agg + (size_t)d * C + lane * 4;
    asm volatile("red.global.add.v4.f32 [%0], {%1, %2, %3, %4};"
                 :: "l"(p), "f"(v.x), "f"(v.y), "f"(v.z), "f"(v.w) : "memory");
    if (cnt != nullptr && lane == 0) atomicAdd(cnt + d, 1);
}

// ---------------------------------------------------------------------------
// HMMA fused dual-matmul layer (split-bf16 emulated fp32):
//   out[n][o] = relu( A1'[n]·W1[o] + A2[n]·W2[o] + bias[o] ),  A1' = A1/deg
//
// 256 thr, tile 128x128, K processed as 4 chunks of 64 (2 passes x 2).
// Warp tile 32x64 (4 M-warps x 2 N-warps), m16n8k16 bf16 mma via ldmatrix.x4.
// Weights pre-split (hi/lo bf16) in global -> cp.async copy.
// SMEM 73728 B -> 2 CTAs/SM.
// ---------------------------------------------------------------------------
#define PITCH  72                       // elements; 144 B row stride
#define SLAB_B (128 * PITCH * 2)        // 18432
#define AH_OFF 0
#define AL_OFF SLAB_B
#define WH_OFF (2 * SLAB_B)
#define WL_OFF (3 * SLAB_B)
#define SMEM_BYTES (4 * SLAB_B)         // 73728

__global__ __launch_bounds__(256, 2) void hmma_layer(
    const float* __restrict__ A1, const float* __restrict__ A2,
    const __nv_bfloat16* __restrict__ whi, const __nv_bfloat16* __restrict__ wlo,
    int s0, int s1,
    const float* __restrict__ bias, const int* __restrict__ cnt,
    float* __restrict__ out, int nrows)
{
    extern __shared__ char sm[];
    const uint32_t smb = smem_u32(sm);
    const int t = threadIdx.x, wid = t >> 5, lane = t & 31;
    const int nb = blockIdx.x * 128;

    const int mBase = (wid & 3) * 32;   // 4 M-warps
    const int nBase = (wid >> 2) * 64;  // 2 N-warps

    // ldmatrix per-lane address offsets
    const int arow = (lane & 7) + ((lane >> 3) & 1) * 8;
    const int acol = (lane >> 4) * 8;
    const int brow = (lane & 7) + (lane >> 4) * 8;
    const int bcol = ((lane >> 3) & 1) * 8;
    const uint32_t aoff0 = ((mBase + arow) * PITCH + acol) * 2;
    const uint32_t aoff1 = aoff0 + 16 * PITCH * 2;
    const uint32_t boff  = ((nBase + brow) * PITCH + bcol) * 2;

    float acc[2][8][4];
#pragma unroll
    for (int mt = 0; mt < 2; mt++)
#pragma unroll
        for (int nt = 0; nt < 8; nt++)
#pragma unroll
            for (int j = 0; j < 4; j++) acc[mt][nt][j] = 0.f;

#pragma unroll 1
    for (int pass = 0; pass < 2; pass++) {
        const float* A = pass ? A2 : A1;
        const __nv_bfloat16* Wh = whi + (size_t)(pass ? s1 : s0) * 16384;
        const __nv_bfloat16* Wl = wlo + (size_t)(pass ? s1 : s0) * 16384;
        const bool scale = (pass == 0) && (cnt != nullptr);

#pragma unroll 1
        for (int chunk = 0; chunk < 2; chunk++) {
            const int k0 = chunk * 64;

            // -- W tile copy (pre-split bf16) via cp.async --
            for (int i = t; i < 2048; i += 256) {
                const int slab = i >> 10;           // 0 hi, 1 lo
                const int r    = (i >> 3) & 127;
                const int seg  = i & 7;
                const uint32_t sa = smb + (slab ? WL_OFF : WH_OFF)
                                  + r * (PITCH * 2) + seg * 16;
                const __nv_bfloat16* g = (slab ? Wl : Wh) + (size_t)r * 128 + k0 + seg * 8;
                cp16(sa, g);
            }
            asm volatile("cp.async.commit_group;" ::: "memory");

            // -- A tile: fp32 load + split to hi/lo bf16 --
            for (int i = t; i < 2048; i += 256) {
                const int r  = i >> 4;
                const int f4 = i & 15;
                const int gn = nb + r;
                float4 v = make_float4(0.f, 0.f, 0.f, 0.f);
                if (gn < nrows) {
                    v = __ldg((const float4*)(A + (size_t)gn * C + k0 + f4 * 4));
                    if (scale) {
                        int cc = __ldg(cnt + gn);
                        float s = 1.f / (float)(cc > 1 ? cc : 1);
                        v.x *= s; v.y *= s; v.z *= s; v.w *= s;
                    }
                }
                uint32_t h0 = packbf2(v.x, v.y);
                uint32_t h1 = packbf2(v.z, v.w);
                float l00 = v.x - __uint_as_float(h0 << 16);
                float l01 = v.y - __uint_as_float(h0 & 0xFFFF0000u);
                float l10 = v.z - __uint_as_float(h1 << 16);
                float l11 = v.w - __uint_as_float(h1 & 0xFFFF0000u);
                uint32_t l0 = packbf2(l00, l01);
                uint32_t l1 = packbf2(l10, l11);
                const size_t so = (size_t)r * (PITCH * 2) + f4 * 8;
                *(uint2*)(sm + AH_OFF + so) = make_uint2(h0, h1);
                *(uint2*)(sm + AL_OFF + so) = make_uint2(l0, l1);
            }
            asm volatile("cp.async.wait_group 0;" ::: "memory");
            __syncthreads();

            // -- MMA: 4 k16 steps --
#pragma unroll
            for (int ks = 0; ks < 4; ks++) {
                uint32_t ah0[4], ah1[4], al0[4], al1[4];
                ldsm4(smb + AH_OFF + aoff0 + ks * 32, ah0);
                ldsm4(smb + AH_OFF + aoff1 + ks * 32, ah1);
                ldsm4(smb + AL_OFF + aoff0 + ks * 32, al0);
                ldsm4(smb + AL_OFF + aoff1 + ks * 32, al1);
#pragma unroll
                for (int p = 0; p < 4; p++) {
                    uint32_t bh[4], bl[4];
                    const uint32_t bo = boff + p * (16 * PITCH * 2) + ks * 32;
                    ldsm4(smb + WH_OFF + bo, bh);
                    ldsm4(smb + WL_OFF + bo, bl);
                    mma16816(acc[0][2 * p],     ah0, bh);
                    mma16816(acc[1][2 * p],     ah1, bh);
                    mma16816(acc[0][2 * p],     al0, bh);
                    mma16816(acc[1][2 * p],     al1, bh);
                    mma16816(acc[0][2 * p],     ah0, bl);
                    mma16816(acc[1][2 * p],     ah1, bl);
                    mma16816(acc[0][2 * p + 1], ah0, bh + 2);
                    mma16816(acc[1][2 * p + 1], ah1, bh + 2);
                    mma16816(acc[0][2 * p + 1], al0, bh + 2);
                    mma16816(acc[1][2 * p + 1], al1, bh + 2);
                    mma16816(acc[0][2 * p + 1], ah0, bl + 2);
                    mma16816(acc[1][2 * p + 1], ah1, bl + 2);
                }
            }
            __syncthreads();
        }
    }

    // -- epilogue: bias + relu, registers -> gmem --
    const int qrow = lane >> 2;
    const int qk   = (lane & 3) * 2;
#pragma unroll
    for (int nt = 0; nt < 8; nt++) {
        const int cl = nBase + nt * 8 + qk;
        const float2 b = __ldg((const float2*)(bias + cl));
#pragma unroll
        for (int mt = 0; mt < 2; mt++) {
            const int r0 = nb + mBase + mt * 16 + qrow;
            if (r0 < nrows) {
                float2 o;
                o.x = fmaxf(acc[mt][nt][0] + b.x, 0.f);
                o.y = fmaxf(acc[mt][nt][1] + b.y, 0.f);
                *(float2*)(out + (size_t)r0 * C + cl) = o;
            }
            const int r1 = r0 + 8;
            if (r1 < nrows) {
                float2 o;
                o.x = fmaxf(acc[mt][nt][2] + b.x, 0.f);
                o.y = fmaxf(acc[mt][nt][3] + b.y, 0.f);
                *(float2*)(out + (size_t)r1 * C + cl) = o;
            }
        }
    }
}

// ---------------------------------------------------------------------------
// launch
// ---------------------------------------------------------------------------
extern "C" void kernel_launch(void* const* d_in, const int* in_sizes, int n_in,
                              void* d_out, int out_size)
{
    const float* x    = (const float*)d_in[0];
    const int*   ei   = (const int*)  d_in[1];
    const float* Wl1  = (const float*)d_in[2];
    const float* Wr1  = (const float*)d_in[3];
    const float* b1   = (const float*)d_in[4];
    const float* Wl2  = (const float*)d_in[5];
    const float* Wr2  = (const float*)d_in[6];
    const float* b2   = (const float*)d_in[7];
    const float* Wlin = (const float*)d_in[8];
    const float* blin = (const float*)d_in[9];
    float*       out  = (float*)d_out;

    const int* src = ei;
    const int* dst = ei + EE;

    void *agg_v, *h1_v, *h2_v, *cnt_v, *whi_v, *wlo_v;
    cudaGetSymbolAddress(&agg_v, g_agg);
    cudaGetSymbolAddress(&h1_v,  g_h1);
    cudaGetSymbolAddress(&h2_v,  g_h2);
    cudaGetSymbolAddress(&cnt_v, g_cnt);
    cudaGetSymbolAddress(&whi_v, g_whi);
    cudaGetSymbolAddress(&wlo_v, g_wlo);
    float* agg = (float*)agg_v;
    float* h1  = (float*)h1_v;
    float* h2  = (float*)h2_v;
    int*   cnt = (int*)cnt_v;
    __nv_bfloat16* whi = (__nv_bfloat16*)whi_v;
    __nv_bfloat16* wlo = (__nv_bfloat16*)wlo_v;

    cudaFuncSetAttribute(hmma_layer,
                         cudaFuncAttributeMaxDynamicSharedMemorySize, SMEM_BYTES);

    const int featN4 = NN * C / 4;
    const int zb     = (featN4 + 255) / 256;
    const int cntN4  = NN / 4;
    const int zcb    = (cntN4 + 255) / 256;
    const int sblk   = EE / 8;
    const int gblk   = (NN + 127) / 128;       // 782
    const int wblk   = (6 * 16384 + 255) / 256;

    // ---- prep: split weights once ----
    split_weights<<<wblk, 256>>>(Wl1, Wr1, Wl2, Wr2, Wlin, whi, wlo);

    // ---- conv1 ----
    zero_f4<<<zb, 256>>>((float4*)agg, featN4);
    zero_f4<<<zcb, 256>>>((float4*)cnt, cntN4);
    scatter_edges<<<sblk, 256>>>(x, src, dst, agg, cnt);
    hmma_layer<<<gblk, 256, SMEM_BYTES>>>(agg, x, whi, wlo, 0, 1, b1, cnt, h1, NN);

    // ---- conv2 ----
    zero_f4<<<zb, 256>>>((float4*)agg, featN4);
    scatter_edges<<<sblk, 256>>>(h1, src, dst, agg, nullptr);
    hmma_layer<<<gblk, 256, SMEM_BYTES>>>(agg, h1, whi, wlo, 2, 3, b2, cnt, h2, NN);

    // ---- JK-cat + linear head ----
    hmma_layer<<<gblk, 256, SMEM_BYTES>>>(h1, h2, whi, wlo, 4, 5, blin, nullptr, out, NN);
}

// round 5
// speedup vs baseline: 2.3202x; 1.4750x over previous
#include <cuda_runtime.h>
#include <cuda_bf16.h>
#include <cstdint>
#include <cstddef>

#define NN 100000
#define EE 1600000
#define C  128

// ---- scratch (device globals: allocation-free) ----
__device__ float g_agg[(size_t)NN * C];
__device__ float g_h1 [(size_t)NN * C];
__device__ float g_h2 [(size_t)NN * C];
__device__ int   g_cnt[NN];          // per-dst degree (histogram)
__device__ int   g_rowptr[NN + 1];   // CSR row pointers (by dst)
__device__ int   g_cursor[NN];       // scatter cursors
__device__ int   g_srcs[EE];         // dst-sorted src indices
__device__ __nv_bfloat16 g_whi[6 * 16384];
__device__ __nv_bfloat16 g_wlo[6 * 16384];

// ---------------------------------------------------------------------------
// helpers
// ---------------------------------------------------------------------------
__device__ __forceinline__ uint32_t smem_u32(const void* p) {
    uint32_t a;
    asm("{ .reg .u64 t; cvta.to.shared.u64 t, %1; cvt.u32.u64 %0, t; }"
        : "=r"(a) : "l"(p));
    return a;
}
__device__ __forceinline__ void cp16(uint32_t saddr, const void* g) {
    asm volatile("cp.async.cg.shared.global [%0], [%1], 16;"
                 :: "r"(saddr), "l"(g) : "memory");
}
__device__ __forceinline__ void ldsm4(uint32_t addr, uint32_t* r) {
    asm volatile("ldmatrix.sync.aligned.m8n8.x4.shared.b16 {%0,%1,%2,%3}, [%4];"
                 : "=r"(r[0]), "=r"(r[1]), "=r"(r[2]), "=r"(r[3]) : "r"(addr));
}
__device__ __forceinline__ void mma16816(float* c, const uint32_t* a, const uint32_t* b) {
    asm volatile(
        "mma.sync.aligned.m16n8k16.row.col.f32.bf16.bf16.f32 "
        "{%0,%1,%2,%3}, {%4,%5,%6,%7}, {%8,%9}, {%0,%1,%2,%3};"
        : "+f"(c[0]), "+f"(c[1]), "+f"(c[2]), "+f"(c[3])
        : "r"(a[0]), "r"(a[1]), "r"(a[2]), "r"(a[3]), "r"(b[0]), "r"(b[1]));
}
__device__ __forceinline__ uint32_t packbf2(float f0, float f1) {
    uint32_t r;
    asm("cvt.rn.bf16x2.f32 %0, %1, %2;" : "=r"(r) : "f"(f1), "f"(f0));
    return r;
}

// ---------------------------------------------------------------------------
// zero fill
// ---------------------------------------------------------------------------
__global__ void zero_i(int* __restrict__ p, int n) {
    int i = blockIdx.x * blockDim.x + threadIdx.x;
    if (i < n) p[i] = 0;
}

// ---------------------------------------------------------------------------
// one-shot weight split
// ---------------------------------------------------------------------------
__global__ void split_weights(const float* __restrict__ Wl1, const float* __restrict__ Wr1,
                              const float* __restrict__ Wl2, const float* __restrict__ Wr2,
                              const float* __restrict__ Wlin,
                              __nv_bfloat16* __restrict__ whi,
                              __nv_bfloat16* __restrict__ wlo)
{
    int i = blockIdx.x * blockDim.x + threadIdx.x;
    if (i >= 6 * 16384) return;
    int s = i >> 14, r = (i >> 7) & 127, k = i & 127;
    float v;
    switch (s) {
        case 0:  v = __ldg(Wl1 + r * 128 + k); break;
        case 1:  v = __ldg(Wr1 + r * 128 + k); break;
        case 2:  v = __ldg(Wl2 + r * 128 + k); break;
        case 3:  v = __ldg(Wr2 + r * 128 + k); break;
        case 4:  v = __ldg(Wlin + r * 256 + k); break;
        default: v = __ldg(Wlin + r * 256 + 128 + k); break;
    }
    __nv_bfloat16 h = __float2bfloat16(v);
    whi[i] = h;
    wlo[i] = __float2bfloat16(v - __bfloat162float(h));
}

// ---------------------------------------------------------------------------
// CSR build: histogram -> scan -> bucket scatter
// ---------------------------------------------------------------------------
__global__ void hist_kernel(const int* __restrict__ dst, int* __restrict__ cnt) {
    int e = blockIdx.x * blockDim.x + threadIdx.x;
    if (e < EE) atomicAdd(cnt + __ldg(dst + e), 1);
}

#define SCAN_T 1024
#define SCAN_R ((NN + SCAN_T - 1) / SCAN_T)   // 98

__global__ __launch_bounds__(SCAN_T) void scan_kernel(
    const int* __restrict__ cnt, int* __restrict__ rowptr, int* __restrict__ cursor)
{
    __shared__ int part[SCAN_T];
    const int t  = threadIdx.x;
    const int lo = t * SCAN_R;
    const int hi = (lo + SCAN_R < NN) ? lo + SCAN_R : NN;

    int s = 0;
    for (int i = lo; i < hi; i++) s += __ldg(cnt + i);
    part[t] = s;
    __syncthreads();

    for (int d = 1; d < SCAN_T; d <<= 1) {
        int x = (t >= d) ? part[t - d] : 0;
        __syncthreads();
        part[t] += x;
        __syncthreads();
    }

    int run = part[t] - s;   // exclusive prefix
    for (int i = lo; i < hi; i++) {
        rowptr[i] = run;
        cursor[i] = run;
        run += __ldg(cnt + i);
    }
    if (hi == NN && lo < NN) rowptr[NN] = run;
    if (t == SCAN_T - 1 && lo >= NN) rowptr[NN] = part[SCAN_T - 1];
}

__global__ void scatter_csr(const int* __restrict__ src, const int* __restrict__ dst,
                            int* __restrict__ cursor, int* __restrict__ srcs)
{
    int e = blockIdx.x * blockDim.x + threadIdx.x;
    if (e >= EE) return;
    int d = __ldg(dst + e);
    int pos = atomicAdd(cursor + d, 1);
    srcs[pos] = __ldg(src + e);
}

// ---------------------------------------------------------------------------
// atomic-free mean aggregation: one warp per node
// ---------------------------------------------------------------------------
__global__ __launch_bounds__(256) void aggregate(
    const float* __restrict__ feat,
    const int*   __restrict__ rowptr,
    const int*   __restrict__ srcs,
    float*       __restrict__ agg)
{
    const int node = blockIdx.x * 8 + (threadIdx.x >> 5);
    const int lane = threadIdx.x & 31;
    if (node >= NN) return;

    const int beg = __ldg(rowptr + node);
    const int end = __ldg(rowptr + node + 1);

    float4 acc = make_float4(0.f, 0.f, 0.f, 0.f);
    int e = beg;
    for (; e + 4 <= end; e += 4) {
        int s0 = __ldg(srcs + e);
        int s1 = __ldg(srcs + e + 1);
        int s2 = __ldg(srcs + e + 2);
        int s3 = __ldg(srcs + e + 3);
        float4 v0 = __ldg((const float4*)(feat + (size_t)s0 * C) + lane);
        float4 v1 = __ldg((const float4*)(feat + (size_t)s1 * C) + lane);
        float4 v2 = __ldg((const float4*)(feat + (size_t)s2 * C) + lane);
        float4 v3 = __ldg((const float4*)(feat + (size_t)s3 * C) + lane);
        v0.x += v1.x; v0.y += v1.y; v0.z += v1.z; v0.w += v1.w;
        v2.x += v3.x; v2.y += v3.y; v2.z += v3.z; v2.w += v3.w;
        acc.x += v0.x + v2.x; acc.y += v0.y + v2.y;
        acc.z += v0.z + v2.z; acc.w += v0.w + v2.w;
    }
    for (; e < end; e++) {
        int s0 = __ldg(srcs + e);
        float4 v0 = __ldg((const float4*)(feat + (size_t)s0 * C) + lane);
        acc.x += v0.x; acc.y += v0.y; acc.z += v0.z; acc.w += v0.w;
    }

    const int deg = end - beg;
    const float inv = 1.f / (float)(deg > 1 ? deg : 1);
    acc.x *= inv; acc.y *= inv; acc.z *= inv; acc.w *= inv;
    *((float4*)(agg + (size_t)node * C) + lane) = acc;
}

// ---------------------------------------------------------------------------
// HMMA fused dual-matmul layer (split-bf16 emulated fp32), as round 4
// ---------------------------------------------------------------------------
#define PITCH  72
#define SLAB_B (128 * PITCH * 2)
#define AH_OFF 0
#define AL_OFF SLAB_B
#define WH_OFF (2 * SLAB_B)
#define WL_OFF (3 * SLAB_B)
#define SMEM_BYTES (4 * SLAB_B)         // 73728

__global__ __launch_bounds__(256, 2) void hmma_layer(
    const float* __restrict__ A1, const float* __restrict__ A2,
    const __nv_bfloat16* __restrict__ whi, const __nv_bfloat16* __restrict__ wlo,
    int s0, int s1,
    const float* __restrict__ bias,
    float* __restrict__ out, int nrows)
{
    extern __shared__ char sm[];
    const uint32_t smb = smem_u32(sm);
    const int t = threadIdx.x, wid = t >> 5, lane = t & 31;
    const int nb = blockIdx.x * 128;

    const int mBase = (wid & 3) * 32;
    const int nBase = (wid >> 2) * 64;

    const int arow = (lane & 7) + ((lane >> 3) & 1) * 8;
    const int acol = (lane >> 4) * 8;
    const int brow = (lane & 7) + (lane >> 4) * 8;
    const int bcol = ((lane >> 3) & 1) * 8;
    const uint32_t aoff0 = ((mBase + arow) * PITCH + acol) * 2;
    const uint32_t aoff1 = aoff0 + 16 * PITCH * 2;
    const uint32_t boff  = ((nBase + brow) * PITCH + bcol) * 2;

    float acc[2][8][4];
#pragma unroll
    for (int mt = 0; mt < 2; mt++)
#pragma unroll
        for (int nt = 0; nt < 8; nt++)
#pragma unroll
            for (int j = 0; j < 4; j++) acc[mt][nt][j] = 0.f;

#pragma unroll 1
    for (int pass = 0; pass < 2; pass++) {
        const float* A = pass ? A2 : A1;
        const __nv_bfloat16* Wh = whi + (size_t)(pass ? s1 : s0) * 16384;
        const __nv_bfloat16* Wl = wlo + (size_t)(pass ? s1 : s0) * 16384;

#pragma unroll 1
        for (int chunk = 0; chunk < 2; chunk++) {
            const int k0 = chunk * 64;

            for (int i = t; i < 2048; i += 256) {
                const int slab = i >> 10;
                const int r    = (i >> 3) & 127;
                const int seg  = i & 7;
                const uint32_t sa = smb + (slab ? WL_OFF : WH_OFF)
                                  + r * (PITCH * 2) + seg * 16;
                const __nv_bfloat16* g = (slab ? Wl : Wh) + (size_t)r * 128 + k0 + seg * 8;
                cp16(sa, g);
            }
            asm volatile("cp.async.commit_group;" ::: "memory");

            for (int i = t; i < 2048; i += 256) {
                const int r  = i >> 4;
                const int f4 = i & 15;
                const int gn = nb + r;
                float4 v = make_float4(0.f, 0.f, 0.f, 0.f);
                if (gn < nrows)
                    v = __ldg((const float4*)(A + (size_t)gn * C + k0 + f4 * 4));
                uint32_t h0 = packbf2(v.x, v.y);
                uint32_t h1 = packbf2(v.z, v.w);
                float l00 = v.x - __uint_as_float(h0 << 16);
                float l01 = v.y - __uint_as_float(h0 & 0xFFFF0000u);
                float l10 = v.z - __uint_as_float(h1 << 16);
                float l11 = v.w - __uint_as_float(h1 & 0xFFFF0000u);
                uint32_t l0 = packbf2(l00, l01);
                uint32_t l1 = packbf2(l10, l11);
                const size_t so = (size_t)r * (PITCH * 2) + f4 * 8;
                *(uint2*)(sm + AH_OFF + so) = make_uint2(h0, h1);
                *(uint2*)(sm + AL_OFF + so) = make_uint2(l0, l1);
            }
            asm volatile("cp.async.wait_group 0;" ::: "memory");
            __syncthreads();

#pragma unroll
            for (int ks = 0; ks < 4; ks++) {
                uint32_t ah0[4], ah1[4], al0[4], al1[4];
                ldsm4(smb + AH_OFF + aoff0 + ks * 32, ah0);
                ldsm4(smb + AH_OFF + aoff1 + ks * 32, ah1);
                ldsm4(smb + AL_OFF + aoff0 + ks * 32, al0);
                ldsm4(smb + AL_OFF + aoff1 + ks * 32, al1);
#pragma unroll
                for (int p = 0; p < 4; p++) {
                    uint32_t bh[4], bl[4];
                    const uint32_t bo = boff + p * (16 * PITCH * 2) + ks * 32;
                    ldsm4(smb + WH_OFF + bo, bh);
                    ldsm4(smb + WL_OFF + bo, bl);
                    mma16816(acc[0][2 * p],     ah0, bh);
                    mma16816(acc[1][2 * p],     ah1, bh);
                    mma16816(acc[0][2 * p],     al0, bh);
                    mma16816(acc[1][2 * p],     al1, bh);
                    mma16816(acc[0][2 * p],     ah0, bl);
                    mma16816(acc[1][2 * p],     ah1, bl);
                    mma16816(acc[0][2 * p + 1], ah0, bh + 2);
                    mma16816(acc[1][2 * p + 1], ah1, bh + 2);
                    mma16816(acc[0][2 * p + 1], al0, bh + 2);
                    mma16816(acc[1][2 * p + 1], al1, bh + 2);
                    mma16816(acc[0][2 * p + 1], ah0, bl + 2);
                    mma16816(acc[1][2 * p + 1], ah1, bl + 2);
                }
            }
            __syncthreads();
        }
    }

    const int qrow = lane >> 2;
    const int qk   = (lane & 3) * 2;
#pragma unroll
    for (int nt = 0; nt < 8; nt++) {
        const int cl = nBase + nt * 8 + qk;
        const float2 b = __ldg((const float2*)(bias + cl));
#pragma unroll
        for (int mt = 0; mt < 2; mt++) {
            const int r0 = nb + mBase + mt * 16 + qrow;
            if (r0 < nrows) {
                float2 o;
                o.x = fmaxf(acc[mt][nt][0] + b.x, 0.f);
                o.y = fmaxf(acc[mt][nt][1] + b.y, 0.f);
                *(float2*)(out + (size_t)r0 * C + cl) = o;
            }
            const int r1 = r0 + 8;
            if (r1 < nrows) {
                float2 o;
                o.x = fmaxf(acc[mt][nt][2] + b.x, 0.f);
                o.y = fmaxf(acc[mt][nt][3] + b.y, 0.f);
                *(float2*)(out + (size_t)r1 * C + cl) = o;
            }
        }
    }
}

// ---------------------------------------------------------------------------
// launch
// ---------------------------------------------------------------------------
extern "C" void kernel_launch(void* const* d_in, const int* in_sizes, int n_in,
                              void* d_out, int out_size)
{
    const float* x    = (const float*)d_in[0];
    const int*   ei   = (const int*)  d_in[1];
    const float* Wl1  = (const float*)d_in[2];
    const float* Wr1  = (const float*)d_in[3];
    const float* b1   = (const float*)d_in[4];
    const float* Wl2  = (const float*)d_in[5];
    const float* Wr2  = (const float*)d_in[6];
    const float* b2   = (const float*)d_in[7];
    const float* Wlin = (const float*)d_in[8];
    const float* blin = (const float*)d_in[9];
    float*       out  = (float*)d_out;

    const int* src = ei;
    const int* dst = ei + EE;

    void *agg_v, *h1_v, *h2_v, *cnt_v, *rp_v, *cur_v, *srcs_v, *whi_v, *wlo_v;
    cudaGetSymbolAddress(&agg_v, g_agg);
    cudaGetSymbolAddress(&h1_v,  g_h1);
    cudaGetSymbolAddress(&h2_v,  g_h2);
    cudaGetSymbolAddress(&cnt_v, g_cnt);
    cudaGetSymbolAddress(&rp_v,  g_rowptr);
    cudaGetSymbolAddress(&cur_v, g_cursor);
    cudaGetSymbolAddress(&srcs_v, g_srcs);
    cudaGetSymbolAddress(&whi_v, g_whi);
    cudaGetSymbolAddress(&wlo_v, g_wlo);
    float* agg = (float*)agg_v;
    float* h1  = (float*)h1_v;
    float* h2  = (float*)h2_v;
    int*   cnt = (int*)cnt_v;
    int*   rowptr = (int*)rp_v;
    int*   cursor = (int*)cur_v;
    int*   srcs   = (int*)srcs_v;
    __nv_bfloat16* whi = (__nv_bfloat16*)whi_v;
    __nv_bfloat16* wlo = (__nv_bfloat16*)wlo_v;

    cudaFuncSetAttribute(hmma_layer,
                         cudaFuncAttributeMaxDynamicSharedMemorySize, SMEM_BYTES);

    const int eblk = (EE + 255) / 256;          // 6250
    const int gblk = (NN + 127) / 128;          // 782
    const int ablk = (NN + 7) / 8;              // 12500
    const int wblk = (6 * 16384 + 255) / 256;

    // ---- prep: weight split + CSR build (once, reused by both convs) ----
    split_weights<<<wblk, 256>>>(Wl1, Wr1, Wl2, Wr2, Wlin, whi, wlo);
    zero_i<<<(NN + 255) / 256, 256>>>(cnt, NN);
    hist_kernel<<<eblk, 256>>>(dst, cnt);
    scan_kernel<<<1, SCAN_T>>>(cnt, rowptr, cursor);
    scatter_csr<<<eblk, 256>>>(src, dst, cursor, srcs);

    // ---- conv1 ----
    aggregate<<<ablk, 256>>>(x, rowptr, srcs, agg);
    hmma_layer<<<gblk, 256, SMEM_BYTES>>>(agg, x, whi, wlo, 0, 1, b1, h1, NN);

    // ---- conv2 ----
    aggregate<<<ablk, 256>>>(h1, rowptr, srcs, agg);
    hmma_layer<<<gblk, 256, SMEM_BYTES>>>(agg, h1, whi, wlo, 2, 3, b2, h2, NN);

    // ---- JK-cat + linear head ----
    hmma_layer<<<gblk, 256, SMEM_BYTES>>>(h1, h2, whi, wlo, 4, 5, blin, out, NN);
}

// round 6
// speedup vs baseline: 3.2563x; 1.4034x over previous
#include <cuda_runtime.h>
#include <cuda_bf16.h>
#include <cstdint>
#include <cstddef>

#define NN 100000
#define EE 1600000
#define C  128
#define NB 98                 // scan blocks: ceil(100000/1024)

// ---- scratch (device globals: allocation-free) ----
__device__ float g_agg[(size_t)NN * C];
__device__ float g_h1 [(size_t)NN * C];
__device__ float g_h2 [(size_t)NN * C];
__device__ int   g_cnt[NN];          // per-dst degree (histogram)
__device__ int   g_rowptr[NN + 1];   // CSR row pointers (by dst)
__device__ int   g_cursor[NN];       // scatter cursors
__device__ int   g_part[NB];         // scan partials
__device__ int   g_srcs[EE];         // dst-sorted src indices
__device__ __nv_bfloat16 g_whi[6 * 16384];
__device__ __nv_bfloat16 g_wlo[6 * 16384];

// ---------------------------------------------------------------------------
// helpers
// ---------------------------------------------------------------------------
__device__ __forceinline__ uint32_t smem_u32(const void* p) {
    uint32_t a;
    asm("{ .reg .u64 t; cvta.to.shared.u64 t, %1; cvt.u32.u64 %0, t; }"
        : "=r"(a) : "l"(p));
    return a;
}
__device__ __forceinline__ void cp16(uint32_t saddr, const void* g) {
    asm volatile("cp.async.cg.shared.global [%0], [%1], 16;"
                 :: "r"(saddr), "l"(g) : "memory");
}
__device__ __forceinline__ void ldsm4(uint32_t addr, uint32_t* r) {
    asm volatile("ldmatrix.sync.aligned.m8n8.x4.shared.b16 {%0,%1,%2,%3}, [%4];"
                 : "=r"(r[0]), "=r"(r[1]), "=r"(r[2]), "=r"(r[3]) : "r"(addr));
}
__device__ __forceinline__ void mma16816(float* c, const uint32_t* a, const uint32_t* b) {
    asm volatile(
        "mma.sync.aligned.m16n8k16.row.col.f32.bf16.bf16.f32 "
        "{%0,%1,%2,%3}, {%4,%5,%6,%7}, {%8,%9}, {%0,%1,%2,%3};"
        : "+f"(c[0]), "+f"(c[1]), "+f"(c[2]), "+f"(c[3])
        : "r"(a[0]), "r"(a[1]), "r"(a[2]), "r"(a[3]), "r"(b[0]), "r"(b[1]));
}
__device__ __forceinline__ uint32_t packbf2(float f0, float f1) {
    uint32_t r;
    asm("cvt.rn.bf16x2.f32 %0, %1, %2;" : "=r"(r) : "f"(f1), "f"(f0));
    return r;
}
__device__ __forceinline__ int warp_iscan(int v, int lane) {
#pragma unroll
    for (int d = 1; d < 32; d <<= 1) {
        int n = __shfl_up_sync(0xFFFFFFFFu, v, d);
        if (lane >= d) v += n;
    }
    return v;
}

// ---------------------------------------------------------------------------
// zero fill
// ---------------------------------------------------------------------------
__global__ void zero_i(int* __restrict__ p, int n) {
    int i = blockIdx.x * blockDim.x + threadIdx.x;
    if (i < n) p[i] = 0;
}

// ---------------------------------------------------------------------------
// one-shot weight split
// ---------------------------------------------------------------------------
__global__ void split_weights(const float* __restrict__ Wl1, const float* __restrict__ Wr1,
                              const float* __restrict__ Wl2, const float* __restrict__ Wr2,
                              const float* __restrict__ Wlin,
                              __nv_bfloat16* __restrict__ whi,
                              __nv_bfloat16* __restrict__ wlo)
{
    int i = blockIdx.x * blockDim.x + threadIdx.x;
    if (i >= 6 * 16384) return;
    int s = i >> 14, r = (i >> 7) & 127, k = i & 127;
    float v;
    switch (s) {
        case 0:  v = __ldg(Wl1 + r * 128 + k); break;
        case 1:  v = __ldg(Wr1 + r * 128 + k); break;
        case 2:  v = __ldg(Wl2 + r * 128 + k); break;
        case 3:  v = __ldg(Wr2 + r * 128 + k); break;
        case 4:  v = __ldg(Wlin + r * 256 + k); break;
        default: v = __ldg(Wlin + r * 256 + 128 + k); break;
    }
    __nv_bfloat16 h = __float2bfloat16(v);
    whi[i] = h;
    wlo[i] = __float2bfloat16(v - __bfloat162float(h));
}

// ---------------------------------------------------------------------------
// CSR build: histogram -> 3-phase scan -> bucket scatter
// ---------------------------------------------------------------------------
__global__ void hist_kernel(const int* __restrict__ dst, int* __restrict__ cnt) {
    int e = blockIdx.x * blockDim.x + threadIdx.x;
    if (e < EE) atomicAdd(cnt + __ldg(dst + e), 1);
}

// phase 1: block-local exclusive scan (1024 thr); rowptr[i] = local excl prefix
__global__ __launch_bounds__(1024) void scan_blk(
    const int* __restrict__ cnt, int* __restrict__ rowptr, int* __restrict__ part)
{
    __shared__ int ws[32];
    const int t = threadIdx.x, lane = t & 31, w = t >> 5;
    const int i = blockIdx.x * 1024 + t;
    const int v = (i < NN) ? __ldg(cnt + i) : 0;

    int x = warp_iscan(v, lane);
    if (lane == 31) ws[w] = x;
    __syncthreads();
    if (w == 0) ws[lane] = warp_iscan(ws[lane], lane);
    __syncthreads();

    const int incl = x + (w ? ws[w - 1] : 0);
    if (i < NN) rowptr[i] = incl - v;
    if (t == 1023) part[blockIdx.x] = incl;
}

// phase 2: exclusive scan of NB=98 partials (single tiny block)
__global__ __launch_bounds__(128) void scan_part(int* __restrict__ part) {
    __shared__ int ws[4];
    const int t = threadIdx.x, lane = t & 31, w = t >> 5;
    const int v = (t < NB) ? part[t] : 0;
    int x = warp_iscan(v, lane);
    if (lane == 31) ws[w] = x;
    __syncthreads();
    if (t == 0) {
        int run = 0;
        for (int j = 0; j < 4; j++) { int s = ws[j]; ws[j] = run; run += s; }
    }
    __syncthreads();
    if (t < NB) part[t] = x - v + ws[w];
}

// phase 3: add block offsets in place; mirror to cursor; set rowptr[NN]
__global__ __launch_bounds__(1024) void scan_add(
    const int* __restrict__ part, int* __restrict__ rowptr, int* __restrict__ cursor)
{
    const int i = blockIdx.x * 1024 + threadIdx.x;
    if (i < NN) {
        int r = rowptr[i] + part[blockIdx.x];
        rowptr[i] = r;
        cursor[i] = r;
    }
    if (i == 0) rowptr[NN] = EE;
}

__global__ void scatter_csr(const int* __restrict__ src, const int* __restrict__ dst,
                            int* __restrict__ cursor, int* __restrict__ srcs)
{
    int e = blockIdx.x * blockDim.x + threadIdx.x;
    if (e >= EE) return;
    int d = __ldg(dst + e);
    int pos = atomicAdd(cursor + d, 1);
    srcs[pos] = __ldg(src + e);
}

// ---------------------------------------------------------------------------
// atomic-free mean aggregation: one warp per node
// ---------------------------------------------------------------------------
__global__ __launch_bounds__(256) void aggregate(
    const float* __restrict__ feat,
    const int*   __restrict__ rowptr,
    const int*   __restrict__ srcs,
    float*       __restrict__ agg)
{
    const int node = blockIdx.x * 8 + (threadIdx.x >> 5);
    const int lane = threadIdx.x & 31;
    if (node >= NN) return;

    const int beg = __ldg(rowptr + node);
    const int end = __ldg(rowptr + node + 1);

    float4 acc = make_float4(0.f, 0.f, 0.f, 0.f);
    int e = beg;
    for (; e + 4 <= end; e += 4) {
        int s0 = __ldg(srcs + e);
        int s1 = __ldg(srcs + e + 1);
        int s2 = __ldg(srcs + e + 2);
        int s3 = __ldg(srcs + e + 3);
        float4 v0 = __ldg((const float4*)(feat + (size_t)s0 * C) + lane);
        float4 v1 = __ldg((const float4*)(feat + (size_t)s1 * C) + lane);
        float4 v2 = __ldg((const float4*)(feat + (size_t)s2 * C) + lane);
        float4 v3 = __ldg((const float4*)(feat + (size_t)s3 * C) + lane);
        v0.x += v1.x; v0.y += v1.y; v0.z += v1.z; v0.w += v1.w;
        v2.x += v3.x; v2.y += v3.y; v2.z += v3.z; v2.w += v3.w;
        acc.x += v0.x + v2.x; acc.y += v0.y + v2.y;
        acc.z += v0.z + v2.z; acc.w += v0.w + v2.w;
    }
    for (; e < end; e++) {
        int s0 = __ldg(srcs + e);
        float4 v0 = __ldg((const float4*)(feat + (size_t)s0 * C) + lane);
        acc.x += v0.x; acc.y += v0.y; acc.z += v0.z; acc.w += v0.w;
    }

    const int deg = end - beg;
    const float inv = 1.f / (float)(deg > 1 ? deg : 1);
    acc.x *= inv; acc.y *= inv; acc.z *= inv; acc.w *= inv;
    *((float4*)(agg + (size_t)node * C) + lane) = acc;
}

// ---------------------------------------------------------------------------
// HMMA fused dual-matmul layer (split-bf16 emulated fp32)
// ---------------------------------------------------------------------------
#define PITCH  72
#define SLAB_B (128 * PITCH * 2)
#define AH_OFF 0
#define AL_OFF SLAB_B
#define WH_OFF (2 * SLAB_B)
#define WL_OFF (3 * SLAB_B)
#define SMEM_BYTES (4 * SLAB_B)         // 73728

__global__ __launch_bounds__(256, 2) void hmma_layer(
    const float* __restrict__ A1, const float* __restrict__ A2,
    const __nv_bfloat16* __restrict__ whi, const __nv_bfloat16* __restrict__ wlo,
    int s0, int s1,
    const float* __restrict__ bias,
    float* __restrict__ out, int nrows)
{
    extern __shared__ char sm[];
    const uint32_t smb = smem_u32(sm);
    const int t = threadIdx.x, wid = t >> 5, lane = t & 31;
    const int nb = blockIdx.x * 128;

    const int mBase = (wid & 3) * 32;
    const int nBase = (wid >> 2) * 64;

    const int arow = (lane & 7) + ((lane >> 3) & 1) * 8;
    const int acol = (lane >> 4) * 8;
    const int brow = (lane & 7) + (lane >> 4) * 8;
    const int bcol = ((lane >> 3) & 1) * 8;
    const uint32_t aoff0 = ((mBase + arow) * PITCH + acol) * 2;
    const uint32_t aoff1 = aoff0 + 16 * PITCH * 2;
    const uint32_t boff  = ((nBase + brow) * PITCH + bcol) * 2;

    float acc[2][8][4];
#pragma unroll
    for (int mt = 0; mt < 2; mt++)
#pragma unroll
        for (int nt = 0; nt < 8; nt++)
#pragma unroll
            for (int j = 0; j < 4; j++) acc[mt][nt][j] = 0.f;

#pragma unroll 1
    for (int pass = 0; pass < 2; pass++) {
        const float* A = pass ? A2 : A1;
        const __nv_bfloat16* Wh = whi + (size_t)(pass ? s1 : s0) * 16384;
        const __nv_bfloat16* Wl = wlo + (size_t)(pass ? s1 : s0) * 16384;

#pragma unroll 1
        for (int chunk = 0; chunk < 2; chunk++) {
            const int k0 = chunk * 64;

            for (int i = t; i < 2048; i += 256) {
                const int slab = i >> 10;
                const int r    = (i >> 3) & 127;
                const int seg  = i & 7;
                const uint32_t sa = smb + (slab ? WL_OFF : WH_OFF)
                                  + r * (PITCH * 2) + seg * 16;
                const __nv_bfloat16* g = (slab ? Wl : Wh) + (size_t)r * 128 + k0 + seg * 8;
                cp16(sa, g);
            }
            asm volatile("cp.async.commit_group;" ::: "memory");

            for (int i = t; i < 2048; i += 256) {
                const int r  = i >> 4;
                const int f4 = i & 15;
                const int gn = nb + r;
                float4 v = make_float4(0.f, 0.f, 0.f, 0.f);
                if (gn < nrows)
                    v = __ldg((const float4*)(A + (size_t)gn * C + k0 + f4 * 4));
                uint32_t h0 = packbf2(v.x, v.y);
                uint32_t h1 = packbf2(v.z, v.w);
                float l00 = v.x - __uint_as_float(h0 << 16);
                float l01 = v.y - __uint_as_float(h0 & 0xFFFF0000u);
                float l10 = v.z - __uint_as_float(h1 << 16);
                float l11 = v.w - __uint_as_float(h1 & 0xFFFF0000u);
                uint32_t l0 = packbf2(l00, l01);
                uint32_t l1 = packbf2(l10, l11);
                const size_t so = (size_t)r * (PITCH * 2) + f4 * 8;
                *(uint2*)(sm + AH_OFF + so) = make_uint2(h0, h1);
                *(uint2*)(sm + AL_OFF + so) = make_uint2(l0, l1);
            }
            asm volatile("cp.async.wait_group 0;" ::: "memory");
            __syncthreads();

#pragma unroll
            for (int ks = 0; ks < 4; ks++) {
                uint32_t ah0[4], ah1[4], al0[4], al1[4];
                ldsm4(smb + AH_OFF + aoff0 + ks * 32, ah0);
                ldsm4(smb + AH_OFF + aoff1 + ks * 32, ah1);
                ldsm4(smb + AL_OFF + aoff0 + ks * 32, al0);
                ldsm4(smb + AL_OFF + aoff1 + ks * 32, al1);
#pragma unroll
                for (int p = 0; p < 4; p++) {
                    uint32_t bh[4], bl[4];
                    const uint32_t bo = boff + p * (16 * PITCH * 2) + ks * 32;
                    ldsm4(smb + WH_OFF + bo, bh);
                    ldsm4(smb + WL_OFF + bo, bl);
                    mma16816(acc[0][2 * p],     ah0, bh);
                    mma16816(acc[1][2 * p],     ah1, bh);
                    mma16816(acc[0][2 * p],     al0, bh);
                    mma16816(acc[1][2 * p],     al1, bh);
                    mma16816(acc[0][2 * p],     ah0, bl);
                    mma16816(acc[1][2 * p],     ah1, bl);
                    mma16816(acc[0][2 * p + 1], ah0, bh + 2);
                    mma16816(acc[1][2 * p + 1], ah1, bh + 2);
                    mma16816(acc[0][2 * p + 1], al0, bh + 2);
                    mma16816(acc[1][2 * p + 1], al1, bh + 2);
                    mma16816(acc[0][2 * p + 1], ah0, bl + 2);
                    mma16816(acc[1][2 * p + 1], ah1, bl + 2);
                }
            }
            __syncthreads();
        }
    }

    const int qrow = lane >> 2;
    const int qk   = (lane & 3) * 2;
#pragma unroll
    for (int nt = 0; nt < 8; nt++) {
        const int cl = nBase + nt * 8 + qk;
        const float2 b = __ldg((const float2*)(bias + cl));
#pragma unroll
        for (int mt = 0; mt < 2; mt++) {
            const int r0 = nb + mBase + mt * 16 + qrow;
            if (r0 < nrows) {
                float2 o;
                o.x = fmaxf(acc[mt][nt][0] + b.x, 0.f);
                o.y = fmaxf(acc[mt][nt][1] + b.y, 0.f);
                *(float2*)(out + (size_t)r0 * C + cl) = o;
            }
            const int r1 = r0 + 8;
            if (r1 < nrows) {
                float2 o;
                o.x = fmaxf(acc[mt][nt][2] + b.x, 0.f);
                o.y = fmaxf(acc[mt][nt][3] + b.y, 0.f);
                *(float2*)(out + (size_t)r1 * C + cl) = o;
            }
        }
    }
}

// ---------------------------------------------------------------------------
// launch
// ---------------------------------------------------------------------------
extern "C" void kernel_launch(void* const* d_in, const int* in_sizes, int n_in,
                              void* d_out, int out_size)
{
    const float* x    = (const float*)d_in[0];
    const int*   ei   = (const int*)  d_in[1];
    const float* Wl1  = (const float*)d_in[2];
    const float* Wr1  = (const float*)d_in[3];
    const float* b1   = (const float*)d_in[4];
    const float* Wl2  = (const float*)d_in[5];
    const float* Wr2  = (const float*)d_in[6];
    const float* b2   = (const float*)d_in[7];
    const float* Wlin = (const float*)d_in[8];
    const float* blin = (const float*)d_in[9];
    float*       out  = (float*)d_out;

    const int* src = ei;
    const int* dst = ei + EE;

    void *agg_v, *h1_v, *h2_v, *cnt_v, *rp_v, *cur_v, *part_v, *srcs_v, *whi_v, *wlo_v;
    cudaGetSymbolAddress(&agg_v, g_agg);
    cudaGetSymbolAddress(&h1_v,  g_h1);
    cudaGetSymbolAddress(&h2_v,  g_h2);
    cudaGetSymbolAddress(&cnt_v, g_cnt);
    cudaGetSymbolAddress(&rp_v,  g_rowptr);
    cudaGetSymbolAddress(&cur_v, g_cursor);
    cudaGetSymbolAddress(&part_v, g_part);
    cudaGetSymbolAddress(&srcs_v, g_srcs);
    cudaGetSymbolAddress(&whi_v, g_whi);
    cudaGetSymbolAddress(&wlo_v, g_wlo);
    float* agg = (float*)agg_v;
    float* h1  = (float*)h1_v;
    float* h2  = (float*)h2_v;
    int*   cnt = (int*)cnt_v;
    int*   rowptr = (int*)rp_v;
    int*   cursor = (int*)cur_v;
    int*   part   = (int*)part_v;
    int*   srcs   = (int*)srcs_v;
    __nv_bfloat16* whi = (__nv_bfloat16*)whi_v;
    __nv_bfloat16* wlo = (__nv_bfloat16*)wlo_v;

    cudaFuncSetAttribute(hmma_layer,
                         cudaFuncAttributeMaxDynamicSharedMemorySize, SMEM_BYTES);

    const int eblk = (EE + 255) / 256;          // 6250
    const int gblk = (NN + 127) / 128;          // 782
    const int ablk = (NN + 7) / 8;              // 12500
    const int wblk = (6 * 16384 + 255) / 256;

    // ---- prep: weight split + CSR build (once, reused by both convs) ----
    split_weights<<<wblk, 256>>>(Wl1, Wr1, Wl2, Wr2, Wlin, whi, wlo);
    zero_i<<<(NN + 255) / 256, 256>>>(cnt, NN);
    hist_kernel<<<eblk, 256>>>(dst, cnt);
    scan_blk<<<NB, 1024>>>(cnt, rowptr, part);
    scan_part<<<1, 128>>>(part);
    scan_add<<<NB, 1024>>>(part, rowptr, cursor);
    scatter_csr<<<eblk, 256>>>(src, dst, cursor, srcs);

    // ---- conv1 ----
    aggregate<<<ablk, 256>>>(x, rowptr, srcs, agg);
    hmma_layer<<<gblk, 256, SMEM_BYTES>>>(agg, x, whi, wlo, 0, 1, b1, h1, NN);

    // ---- conv2 ----
    aggregate<<<ablk, 256>>>(h1, rowptr, srcs, agg);
    hmma_layer<<<gblk, 256, SMEM_BYTES>>>(agg, h1, whi, wlo, 2, 3, b2, h2, NN);

    // ---- JK-cat + linear head ----
    hmma_layer<<<gblk, 256, SMEM_BYTES>>>(h1, h2, whi, wlo, 4, 5, blin, out, NN);
}